// round 5
// baseline (speedup 1.0000x reference)
#include <cuda_runtime.h>
#include <cuda_bf16.h>
#include <math.h>

#define T_  128
#define B_  128
#define I_  128
#define H_  512
#define W_  16
#define H4_ 2048
#define NBLK 128
#define TPB 256

typedef unsigned long long ull;

// ---------------- device globals (static scratch; no allocs) ----------------
__device__ __align__(16) float g_PxT[(size_t)T_ * H4_ * B_];  // [t][j][b]
__device__ __align__(16) float g_QxT[(size_t)T_ * H_ * B_];   // [t][q][b]
__device__ __align__(16) float g_Vbuf[(size_t)W_ * B_ * H_];  // [w][b][k]
__device__ __align__(16) float g_h[2][H_ * B_];               // [k][b], double buffered
__device__ __align__(16) float g_c[H_ * B_];                  // [k][b]
__device__ __align__(16) float g_at[H_ * B_];                 // [k][b]
__device__ __align__(16) float g_q[B_ * H_];                  // [b][q]

__device__ unsigned g_cnt = 0;
__device__ volatile unsigned g_gen = 0;

// ---------------- packed fp32x2 helpers ----------------
__device__ __forceinline__ ull pk2(float x) {
    ull r; asm("mov.b64 %0, {%1, %2};" : "=l"(r) : "f"(x), "f"(x)); return r;
}
__device__ __forceinline__ void fma2(ull& d, ull a, ull b) {
    asm("fma.rn.f32x2 %0, %1, %2, %3;" : "=l"(d) : "l"(a), "l"(b), "l"(d));
}
__device__ __forceinline__ void upk2(ull v, float& lo, float& hi) {
    asm("mov.b64 {%0, %1}, %2;" : "=f"(lo), "=f"(hi) : "l"(v));
}
union F4U2 { float4 f4; struct { ull a, b; } u; };

// ---------------- grid barrier (all 128 CTAs resident) ----------------
__device__ __forceinline__ void grid_bar() {
    __syncthreads();
    if (threadIdx.x == 0) {
        __threadfence();
        unsigned gen = g_gen;
        if (atomicAdd(&g_cnt, 1u) == NBLK - 1u) {
            g_cnt = 0;
            __threadfence();
            g_gen = gen + 1u;
        } else {
            while (g_gen == gen) { __nanosleep(64); }
        }
        __threadfence();
    }
    __syncthreads();
}

// ---------------- precompute: PxT[t][j][b] = x_t@Wi + bi + ba ----------------
__global__ void precompA(const float* __restrict__ x, const float* __restrict__ Wi,
                         const float* __restrict__ bi, const float* __restrict__ ba) {
    extern __shared__ float xs[];          // [128][129]
    __shared__ float Wis[128][32];
    int t = blockIdx.x, j0 = blockIdx.y * 32;
    const float* xt = x + (size_t)t * B_ * I_;
    for (int i = threadIdx.x; i < B_ * I_; i += TPB)
        xs[(i >> 7) * 129 + (i & 127)] = xt[i];
    for (int i = threadIdx.x; i < 128 * 32; i += TPB) {
        int k = i >> 5, jl = i & 31;
        Wis[k][jl] = Wi[k * H4_ + j0 + jl];
    }
    __syncthreads();
    int b = threadIdx.x & 127, jh = (threadIdx.x >> 7) * 16;
    float acc[16];
#pragma unroll
    for (int d = 0; d < 16; d++) acc[d] = 0.f;
    for (int k = 0; k < I_; k++) {
        float xv = xs[b * 129 + k];
        float4 w0 = *(const float4*)&Wis[k][jh + 0];
        float4 w1 = *(const float4*)&Wis[k][jh + 4];
        float4 w2 = *(const float4*)&Wis[k][jh + 8];
        float4 w3 = *(const float4*)&Wis[k][jh + 12];
        acc[0] += xv * w0.x; acc[1] += xv * w0.y; acc[2] += xv * w0.z; acc[3] += xv * w0.w;
        acc[4] += xv * w1.x; acc[5] += xv * w1.y; acc[6] += xv * w1.z; acc[7] += xv * w1.w;
        acc[8] += xv * w2.x; acc[9] += xv * w2.y; acc[10] += xv * w2.z; acc[11] += xv * w2.w;
        acc[12] += xv * w3.x; acc[13] += xv * w3.y; acc[14] += xv * w3.z; acc[15] += xv * w3.w;
    }
#pragma unroll
    for (int d = 0; d < 16; d++) {
        int j = j0 + jh + d;
        g_PxT[((size_t)t * H4_ + j) * B_ + b] = acc[d] + bi[j] + ba[j];
    }
}

// ---------------- precompute: QxT[t][q][b] = x_t@Wq[:I] + bq ----------------
__global__ void precompB(const float* __restrict__ x, const float* __restrict__ Wq,
                         const float* __restrict__ bq) {
    extern __shared__ float xs[];          // [128][129]
    __shared__ float Wqs[128][32];
    int t = blockIdx.x, j0 = blockIdx.y * 32;
    const float* xt = x + (size_t)t * B_ * I_;
    for (int i = threadIdx.x; i < B_ * I_; i += TPB)
        xs[(i >> 7) * 129 + (i & 127)] = xt[i];
    for (int i = threadIdx.x; i < 128 * 32; i += TPB) {
        int k = i >> 5, jl = i & 31;
        Wqs[k][jl] = Wq[k * H_ + j0 + jl];
    }
    __syncthreads();
    int b = threadIdx.x & 127, jh = (threadIdx.x >> 7) * 16;
    float acc[16];
#pragma unroll
    for (int d = 0; d < 16; d++) acc[d] = 0.f;
    for (int k = 0; k < I_; k++) {
        float xv = xs[b * 129 + k];
        float4 w0 = *(const float4*)&Wqs[k][jh + 0];
        float4 w1 = *(const float4*)&Wqs[k][jh + 4];
        float4 w2 = *(const float4*)&Wqs[k][jh + 8];
        float4 w3 = *(const float4*)&Wqs[k][jh + 12];
        acc[0] += xv * w0.x; acc[1] += xv * w0.y; acc[2] += xv * w0.z; acc[3] += xv * w0.w;
        acc[4] += xv * w1.x; acc[5] += xv * w1.y; acc[6] += xv * w1.z; acc[7] += xv * w1.w;
        acc[8] += xv * w2.x; acc[9] += xv * w2.y; acc[10] += xv * w2.z; acc[11] += xv * w2.w;
        acc[12] += xv * w3.x; acc[13] += xv * w3.y; acc[14] += xv * w3.z; acc[15] += xv * w3.w;
    }
#pragma unroll
    for (int d = 0; d < 16; d++) {
        int j = j0 + jh + d;
        g_QxT[((size_t)t * H_ + j) * B_ + b] = acc[d] + bq[j];
    }
}

// ---------------- persistent main recurrence kernel ----------------
// dyn smem layout (floats):
//  sWh[512*16] | sWa[512*16] | sWq[512*4] | sWv[512*4] | sPre[16*128] | stA[64*128] | stB[64*128]
#define SM_WH 0
#define SM_WA 8192
#define SM_WQ 16384
#define SM_WV 18432
#define SM_PRE 20480
#define SM_STA 22528
#define SM_STB 30720
#define SM_FLOATS 38912
#define SM_BYTES (SM_FLOATS * 4)

__global__ void __launch_bounds__(TPB, 1)
larnn_main(const float* __restrict__ Wh, const float* __restrict__ Wv,
           const float* __restrict__ bv, const float* __restrict__ Wq,
           const float* __restrict__ Wa, float* __restrict__ out) {
    extern __shared__ float sm[];
    float* sWh = sm + SM_WH;
    float* sWa = sm + SM_WA;
    float* sWq = sm + SM_WQ;
    float* sWv = sm + SM_WV;
    float* sPre = sm + SM_PRE;
    float* stA = sm + SM_STA;
    float* stB = sm + SM_STB;
    __shared__ float sQ[H_];
    __shared__ float sSc[W_];
    __shared__ float sP[W_];
    __shared__ float sBv[4];

    const int cta = blockIdx.x;
    const int tid = threadIdx.x;
    const int b_lane = tid & 127;
    const int half = tid >> 7;
    const float isdk = 0.04419417382415922f;  // 1/sqrt(512)

    // --- load resident weight slices (once) ---
    for (int i = tid; i < 512 * 16; i += TPB) {
        int k = i >> 4, jj = i & 15;
        int col = (jj >> 2) * 512 + cta * 4 + (jj & 3);
        sWh[i] = Wh[k * H4_ + col];
        sWa[i] = Wa[k * H4_ + col];
    }
    for (int i = tid; i < 512 * 4; i += TPB) {
        int k = i >> 2, d = i & 3;
        sWq[i] = Wq[(I_ + k) * H_ + cta * 4 + d];
        sWv[i] = Wv[k * H_ + cta * 4 + d];
    }
    if (tid < 4) sBv[tid] = bv[cta * 4 + tid];
    // --- zero initial state for owned columns ---
    for (int i = tid; i < 4 * B_; i += TPB) {
        int d = i >> 7, b = i & 127;
        g_h[0][(cta * 4 + d) * B_ + b] = 0.f;
        g_c[(cta * 4 + d) * B_ + b] = 0.f;
    }
    grid_bar();

    for (int t = 0; t < T_; t++) {
        const float* hT = g_h[t & 1];
        float* hTn = g_h[(t & 1) ^ 1];

        // ===== Phase A: Vnew = c@Wv+bv (half 0), Q = Qx + h@WqH (half 1) =====
        {
            float acc[4];
            if (half == 0) {
                acc[0] = sBv[0]; acc[1] = sBv[1]; acc[2] = sBv[2]; acc[3] = sBv[3];
            } else {
#pragma unroll
                for (int d = 0; d < 4; d++)
                    acc[d] = __ldcg(&g_QxT[((size_t)t * H_ + cta * 4 + d) * B_ + b_lane]);
            }
            for (int k0 = 0; k0 < H_; k0 += 64) {
                __syncthreads();
                const float4* src_h = (const float4*)(hT + k0 * B_);
                const float4* src_c = (const float4*)(g_c + k0 * B_);
                for (int i = tid; i < 2048; i += TPB) {
                    ((float4*)stA)[i] = __ldcg(&src_h[i]);
                    ((float4*)stB)[i] = __ldcg(&src_c[i]);
                }
                __syncthreads();
                const float* src = (half == 0) ? stB : stA;
                const float* w = (half == 0) ? sWv : sWq;
#pragma unroll 4
                for (int kk = 0; kk < 64; kk++) {
                    float v = src[kk * 128 + b_lane];
                    float4 wv = *(const float4*)&w[(k0 + kk) * 4];
                    acc[0] += v * wv.x; acc[1] += v * wv.y;
                    acc[2] += v * wv.z; acc[3] += v * wv.w;
                }
            }
            int slot = t & (W_ - 1);
            if (half == 0) {
#pragma unroll
                for (int d = 0; d < 4; d++)
                    g_Vbuf[((size_t)slot * B_ + b_lane) * H_ + cta * 4 + d] = acc[d];
            } else {
#pragma unroll
                for (int d = 0; d < 4; d++)
                    g_q[b_lane * H_ + cta * 4 + d] = acc[d];
            }
        }
        grid_bar();

        // ===== Phase B: attention for batch row bb = cta =====
        {
            const int bb = cta;
            for (int i = tid; i < H_; i += TPB) sQ[i] = __ldcg(&g_q[bb * H_ + i]);
            __syncthreads();
            int wid = tid >> 5, lane = tid & 31;
#pragma unroll
            for (int wi = 0; wi < 2; wi++) {
                int w = wid * 2 + wi;
                float s = 0.f;
#pragma unroll 4
                for (int k = lane; k < H_; k += 32)
                    s += sQ[k] * __ldcg(&g_Vbuf[((size_t)w * B_ + bb) * H_ + k]);
#pragma unroll
                for (int o = 16; o; o >>= 1) s += __shfl_xor_sync(0xffffffffu, s, o);
                if (lane == 0) sSc[w] = s * isdk;
            }
            __syncthreads();
            if (tid == 0) {
                int nv = (t + 1 < W_) ? (t + 1) : W_;
                float m = -1e30f;
                for (int w = 0; w < nv; w++) m = fmaxf(m, sSc[w]);
                float e[W_], ssum = 0.f;
                for (int w = 0; w < W_; w++) {
                    e[w] = (w < nv) ? expf(sSc[w] - m) : 0.f;
                    ssum += e[w];
                }
                float inv = 1.f / ssum;
                for (int w = 0; w < W_; w++) sP[w] = e[w] * inv;
            }
            __syncthreads();
            for (int k = tid; k < H_; k += TPB) {
                float a = 0.f;
#pragma unroll
                for (int w = 0; w < W_; w++)
                    a += sP[w] * __ldcg(&g_Vbuf[((size_t)w * B_ + bb) * H_ + k]);
                g_at[k * B_ + bb] = a;
            }
        }
        grid_bar();

        // ===== Phase C: preact = Px + h@Wh + attn@Wa; gates; state update =====
        {
            ull acc2[4];
            acc2[0] = acc2[1] = acc2[2] = acc2[3] = pk2(0.f);
            const int jjb = half * 8;
            for (int k0 = 0; k0 < H_; k0 += 64) {
                __syncthreads();
                const float4* src_h = (const float4*)(hT + k0 * B_);
                const float4* src_a = (const float4*)(g_at + k0 * B_);
                for (int i = tid; i < 2048; i += TPB) {
                    ((float4*)stA)[i] = __ldcg(&src_h[i]);
                    ((float4*)stB)[i] = __ldcg(&src_a[i]);
                }
                __syncthreads();
#pragma unroll 2
                for (int kk = 0; kk < 64; kk++) {
                    ull hv2 = pk2(stA[kk * 128 + b_lane]);
                    ull av2 = pk2(stB[kk * 128 + b_lane]);
                    F4U2 wh0, wh1, wa0, wa1;
                    wh0.f4 = *(const float4*)&sWh[(k0 + kk) * 16 + jjb];
                    wh1.f4 = *(const float4*)&sWh[(k0 + kk) * 16 + jjb + 4];
                    wa0.f4 = *(const float4*)&sWa[(k0 + kk) * 16 + jjb];
                    wa1.f4 = *(const float4*)&sWa[(k0 + kk) * 16 + jjb + 4];
                    fma2(acc2[0], wh0.u.a, hv2); fma2(acc2[1], wh0.u.b, hv2);
                    fma2(acc2[2], wh1.u.a, hv2); fma2(acc2[3], wh1.u.b, hv2);
                    fma2(acc2[0], wa0.u.a, av2); fma2(acc2[1], wa0.u.b, av2);
                    fma2(acc2[2], wa1.u.a, av2); fma2(acc2[3], wa1.u.b, av2);
                }
            }
#pragma unroll
            for (int p2 = 0; p2 < 4; p2++) {
                float lo, hi;
                upk2(acc2[p2], lo, hi);
                int jj0 = jjb + p2 * 2;
                int jl = (jj0 >> 2) * 512 + cta * 4 + (jj0 & 3);
                int jh2 = ((jj0 + 1) >> 2) * 512 + cta * 4 + ((jj0 + 1) & 3);
                sPre[jj0 * 128 + b_lane] =
                    lo + __ldcg(&g_PxT[((size_t)t * H4_ + jl) * B_ + b_lane]);
                sPre[(jj0 + 1) * 128 + b_lane] =
                    hi + __ldcg(&g_PxT[((size_t)t * H4_ + jh2) * B_ + b_lane]);
            }
            __syncthreads();
            if (half == 0) {
                int b = b_lane;
#pragma unroll
                for (int d = 0; d < 4; d++) {
                    float pi = sPre[(0 + d) * 128 + b];
                    float pf = sPre[(4 + d) * 128 + b];
                    float po = sPre[(8 + d) * 128 + b];
                    float pg = sPre[(12 + d) * 128 + b];
                    float iv = 1.f / (1.f + expf(-pi));
                    float fv = 1.f / (1.f + expf(-pf));
                    float ov = 1.f / (1.f + expf(-po));
                    float gv = tanhf(pg);
                    int col = cta * 4 + d;
                    float cold = __ldcg(&g_c[col * B_ + b]);
                    float cnew = cold * fv + iv * gv;
                    float hnew = ov * tanhf(cnew);
                    g_c[col * B_ + b] = cnew;
                    hTn[col * B_ + b] = hnew;
                    out[((size_t)t * B_ + b) * H_ + col] = hnew;
                }
            }
        }
        grid_bar();
    }
}

// ---------------- launch ----------------
extern "C" void kernel_launch(void* const* d_in, const int* in_sizes, int n_in,
                              void* d_out, int out_size) {
    const float* x  = (const float*)d_in[0];
    const float* Wi = (const float*)d_in[1];
    const float* bi = (const float*)d_in[2];
    const float* Wh = (const float*)d_in[3];
    const float* Wv = (const float*)d_in[4];
    const float* bv = (const float*)d_in[5];
    const float* Wq = (const float*)d_in[6];
    const float* bq = (const float*)d_in[7];
    const float* Wa = (const float*)d_in[8];
    const float* ba = (const float*)d_in[9];
    float* out = (float*)d_out;

    static const int PRE_SMEM = 128 * 129 * 4;  // 66048 B
    cudaFuncSetAttribute(precompA, cudaFuncAttributeMaxDynamicSharedMemorySize, PRE_SMEM);
    cudaFuncSetAttribute(precompB, cudaFuncAttributeMaxDynamicSharedMemorySize, PRE_SMEM);
    cudaFuncSetAttribute(larnn_main, cudaFuncAttributeMaxDynamicSharedMemorySize, SM_BYTES);

    precompA<<<dim3(T_, H4_ / 32), TPB, PRE_SMEM>>>(x, Wi, bi, ba);
    precompB<<<dim3(T_, H_ / 32), TPB, PRE_SMEM>>>(x, Wq, bq);
    larnn_main<<<NBLK, TPB, SM_BYTES>>>(Wh, Wv, bv, Wq, Wa, out);
}

// round 6
// speedup vs baseline: 1.0008x; 1.0008x over previous
#include <cuda_runtime.h>
#include <cuda_bf16.h>
#include <math.h>

#define T_  128
#define B_  128
#define I_  128
#define H_  512
#define W_  16
#define H4_ 2048
#define NBLK 128
#define TPB 256

typedef unsigned long long ull;

// ---------------- device globals (static scratch; no allocs) ----------------
__device__ __align__(16) float g_PxT[(size_t)T_ * H4_ * B_];  // [t][j][b]
__device__ __align__(16) float g_QxT[(size_t)T_ * H_ * B_];   // [t][q][b]
__device__ __align__(16) float g_Vbuf[(size_t)W_ * B_ * H_];  // [w][b][k]
__device__ __align__(16) float g_h[2][H_ * B_];               // [k][b], double buffered
__device__ __align__(16) float g_c[H_ * B_];                  // [k][b]
__device__ __align__(16) float g_at[H_ * B_];                 // [k][b]
__device__ __align__(16) float g_q[B_ * H_];                  // [b][q]

__device__ unsigned g_cnt = 0;
__device__ volatile unsigned g_gen = 0;

// ---------------- packed fp32x2 helpers ----------------
__device__ __forceinline__ ull pk2(float x) {
    ull r; asm("mov.b64 %0, {%1, %2};" : "=l"(r) : "f"(x), "f"(x)); return r;
}
__device__ __forceinline__ void fma2(ull& d, ull a, ull b) {
    asm("fma.rn.f32x2 %0, %1, %2, %3;" : "=l"(d) : "l"(a), "l"(b), "l"(d));
}
__device__ __forceinline__ void upk2(ull v, float& lo, float& hi) {
    asm("mov.b64 {%0, %1}, %2;" : "=f"(lo), "=f"(hi) : "l"(v));
}
union F4U2 { float4 f4; struct { ull a, b; } u; };

// ---------------- grid barrier (all 128 CTAs resident) ----------------
__device__ __forceinline__ void grid_bar() {
    __syncthreads();
    if (threadIdx.x == 0) {
        __threadfence();
        unsigned gen = g_gen;
        if (atomicAdd(&g_cnt, 1u) == NBLK - 1u) {
            g_cnt = 0;
            __threadfence();
            g_gen = gen + 1u;
        } else {
            while (g_gen == gen) { __nanosleep(64); }
        }
        __threadfence();
    }
    __syncthreads();
}

// ---------------- precompute: PxT[t][j][b] = x_t@Wi + bi + ba ----------------
__global__ void precompA(const float* __restrict__ x, const float* __restrict__ Wi,
                         const float* __restrict__ bi, const float* __restrict__ ba) {
    extern __shared__ float xs[];          // [128][129]
    __shared__ float Wis[128][32];
    int t = blockIdx.x, j0 = blockIdx.y * 32;
    const float* xt = x + (size_t)t * B_ * I_;
    for (int i = threadIdx.x; i < B_ * I_; i += TPB)
        xs[(i >> 7) * 129 + (i & 127)] = xt[i];
    for (int i = threadIdx.x; i < 128 * 32; i += TPB) {
        int k = i >> 5, jl = i & 31;
        Wis[k][jl] = Wi[k * H4_ + j0 + jl];
    }
    __syncthreads();
    int b = threadIdx.x & 127, jh = (threadIdx.x >> 7) * 16;
    float acc[16];
#pragma unroll
    for (int d = 0; d < 16; d++) acc[d] = 0.f;
    for (int k = 0; k < I_; k++) {
        float xv = xs[b * 129 + k];
        float4 w0 = *(const float4*)&Wis[k][jh + 0];
        float4 w1 = *(const float4*)&Wis[k][jh + 4];
        float4 w2 = *(const float4*)&Wis[k][jh + 8];
        float4 w3 = *(const float4*)&Wis[k][jh + 12];
        acc[0] += xv * w0.x; acc[1] += xv * w0.y; acc[2] += xv * w0.z; acc[3] += xv * w0.w;
        acc[4] += xv * w1.x; acc[5] += xv * w1.y; acc[6] += xv * w1.z; acc[7] += xv * w1.w;
        acc[8] += xv * w2.x; acc[9] += xv * w2.y; acc[10] += xv * w2.z; acc[11] += xv * w2.w;
        acc[12] += xv * w3.x; acc[13] += xv * w3.y; acc[14] += xv * w3.z; acc[15] += xv * w3.w;
    }
#pragma unroll
    for (int d = 0; d < 16; d++) {
        int j = j0 + jh + d;
        g_PxT[((size_t)t * H4_ + j) * B_ + b] = acc[d] + bi[j] + ba[j];
    }
}

// ---------------- precompute: QxT[t][q][b] = x_t@Wq[:I] + bq ----------------
__global__ void precompB(const float* __restrict__ x, const float* __restrict__ Wq,
                         const float* __restrict__ bq) {
    extern __shared__ float xs[];          // [128][129]
    __shared__ float Wqs[128][32];
    int t = blockIdx.x, j0 = blockIdx.y * 32;
    const float* xt = x + (size_t)t * B_ * I_;
    for (int i = threadIdx.x; i < B_ * I_; i += TPB)
        xs[(i >> 7) * 129 + (i & 127)] = xt[i];
    for (int i = threadIdx.x; i < 128 * 32; i += TPB) {
        int k = i >> 5, jl = i & 31;
        Wqs[k][jl] = Wq[k * H_ + j0 + jl];
    }
    __syncthreads();
    int b = threadIdx.x & 127, jh = (threadIdx.x >> 7) * 16;
    float acc[16];
#pragma unroll
    for (int d = 0; d < 16; d++) acc[d] = 0.f;
    for (int k = 0; k < I_; k++) {
        float xv = xs[b * 129 + k];
        float4 w0 = *(const float4*)&Wqs[k][jh + 0];
        float4 w1 = *(const float4*)&Wqs[k][jh + 4];
        float4 w2 = *(const float4*)&Wqs[k][jh + 8];
        float4 w3 = *(const float4*)&Wqs[k][jh + 12];
        acc[0] += xv * w0.x; acc[1] += xv * w0.y; acc[2] += xv * w0.z; acc[3] += xv * w0.w;
        acc[4] += xv * w1.x; acc[5] += xv * w1.y; acc[6] += xv * w1.z; acc[7] += xv * w1.w;
        acc[8] += xv * w2.x; acc[9] += xv * w2.y; acc[10] += xv * w2.z; acc[11] += xv * w2.w;
        acc[12] += xv * w3.x; acc[13] += xv * w3.y; acc[14] += xv * w3.z; acc[15] += xv * w3.w;
    }
#pragma unroll
    for (int d = 0; d < 16; d++) {
        int j = j0 + jh + d;
        g_QxT[((size_t)t * H_ + j) * B_ + b] = acc[d] + bq[j];
    }
}

// ---------------- persistent main recurrence kernel ----------------
// dyn smem layout (floats):
//  sWh[512*16] | sWa[512*16] | sWq[512*4] | sWv[512*4] | sPre[16*128] | stA[64*128] | stB[64*128]
#define SM_WH 0
#define SM_WA 8192
#define SM_WQ 16384
#define SM_WV 18432
#define SM_PRE 20480
#define SM_STA 22528
#define SM_STB 30720
#define SM_FLOATS 38912
#define SM_BYTES (SM_FLOATS * 4)

__global__ void __launch_bounds__(TPB, 1)
larnn_main(const float* __restrict__ Wh, const float* __restrict__ Wv,
           const float* __restrict__ bv, const float* __restrict__ Wq,
           const float* __restrict__ Wa, float* __restrict__ out) {
    extern __shared__ float sm[];
    float* sWh = sm + SM_WH;
    float* sWa = sm + SM_WA;
    float* sWq = sm + SM_WQ;
    float* sWv = sm + SM_WV;
    float* sPre = sm + SM_PRE;
    float* stA = sm + SM_STA;
    float* stB = sm + SM_STB;
    __shared__ float sQ[H_];
    __shared__ float sSc[W_];
    __shared__ float sP[W_];
    __shared__ float sBv[4];

    const int cta = blockIdx.x;
    const int tid = threadIdx.x;
    const int b_lane = tid & 127;
    const int half = tid >> 7;
    const float isdk = 0.04419417382415922f;  // 1/sqrt(512)

    // --- load resident weight slices (once) ---
    for (int i = tid; i < 512 * 16; i += TPB) {
        int k = i >> 4, jj = i & 15;
        int col = (jj >> 2) * 512 + cta * 4 + (jj & 3);
        sWh[i] = Wh[k * H4_ + col];
        sWa[i] = Wa[k * H4_ + col];
    }
    for (int i = tid; i < 512 * 4; i += TPB) {
        int k = i >> 2, d = i & 3;
        sWq[i] = Wq[(I_ + k) * H_ + cta * 4 + d];
        sWv[i] = Wv[k * H_ + cta * 4 + d];
    }
    if (tid < 4) sBv[tid] = bv[cta * 4 + tid];
    // --- zero initial state for owned columns ---
    for (int i = tid; i < 4 * B_; i += TPB) {
        int d = i >> 7, b = i & 127;
        g_h[0][(cta * 4 + d) * B_ + b] = 0.f;
        g_c[(cta * 4 + d) * B_ + b] = 0.f;
    }
    grid_bar();

    for (int t = 0; t < T_; t++) {
        const float* hT = g_h[t & 1];
        float* hTn = g_h[(t & 1) ^ 1];

        // ===== Phase A: Vnew = c@Wv+bv (half 0), Q = Qx + h@WqH (half 1) =====
        {
            float acc[4];
            if (half == 0) {
                acc[0] = sBv[0]; acc[1] = sBv[1]; acc[2] = sBv[2]; acc[3] = sBv[3];
            } else {
#pragma unroll
                for (int d = 0; d < 4; d++)
                    acc[d] = __ldcg(&g_QxT[((size_t)t * H_ + cta * 4 + d) * B_ + b_lane]);
            }
            for (int k0 = 0; k0 < H_; k0 += 64) {
                __syncthreads();
                const float4* src_h = (const float4*)(hT + k0 * B_);
                const float4* src_c = (const float4*)(g_c + k0 * B_);
                for (int i = tid; i < 2048; i += TPB) {
                    ((float4*)stA)[i] = __ldcg(&src_h[i]);
                    ((float4*)stB)[i] = __ldcg(&src_c[i]);
                }
                __syncthreads();
                const float* src = (half == 0) ? stB : stA;
                const float* w = (half == 0) ? sWv : sWq;
#pragma unroll 4
                for (int kk = 0; kk < 64; kk++) {
                    float v = src[kk * 128 + b_lane];
                    float4 wv = *(const float4*)&w[(k0 + kk) * 4];
                    acc[0] += v * wv.x; acc[1] += v * wv.y;
                    acc[2] += v * wv.z; acc[3] += v * wv.w;
                }
            }
            int slot = t & (W_ - 1);
            if (half == 0) {
#pragma unroll
                for (int d = 0; d < 4; d++)
                    g_Vbuf[((size_t)slot * B_ + b_lane) * H_ + cta * 4 + d] = acc[d];
            } else {
#pragma unroll
                for (int d = 0; d < 4; d++)
                    g_q[b_lane * H_ + cta * 4 + d] = acc[d];
            }
        }
        grid_bar();

        // ===== Phase B: attention for batch row bb = cta =====
        {
            const int bb = cta;
            for (int i = tid; i < H_; i += TPB) sQ[i] = __ldcg(&g_q[bb * H_ + i]);
            __syncthreads();
            int wid = tid >> 5, lane = tid & 31;
#pragma unroll
            for (int wi = 0; wi < 2; wi++) {
                int w = wid * 2 + wi;
                float s = 0.f;
#pragma unroll 4
                for (int k = lane; k < H_; k += 32)
                    s += sQ[k] * __ldcg(&g_Vbuf[((size_t)w * B_ + bb) * H_ + k]);
#pragma unroll
                for (int o = 16; o; o >>= 1) s += __shfl_xor_sync(0xffffffffu, s, o);
                if (lane == 0) sSc[w] = s * isdk;
            }
            __syncthreads();
            if (tid == 0) {
                int nv = (t + 1 < W_) ? (t + 1) : W_;
                float m = -1e30f;
                for (int w = 0; w < nv; w++) m = fmaxf(m, sSc[w]);
                float e[W_], ssum = 0.f;
                for (int w = 0; w < W_; w++) {
                    e[w] = (w < nv) ? expf(sSc[w] - m) : 0.f;
                    ssum += e[w];
                }
                float inv = 1.f / ssum;
                for (int w = 0; w < W_; w++) sP[w] = e[w] * inv;
            }
            __syncthreads();
            for (int k = tid; k < H_; k += TPB) {
                float a = 0.f;
#pragma unroll
                for (int w = 0; w < W_; w++)
                    a += sP[w] * __ldcg(&g_Vbuf[((size_t)w * B_ + bb) * H_ + k]);
                g_at[k * B_ + bb] = a;
            }
        }
        grid_bar();

        // ===== Phase C: preact = Px + h@Wh + attn@Wa; gates; state update =====
        {
            ull acc2[4];
            acc2[0] = acc2[1] = acc2[2] = acc2[3] = pk2(0.f);
            const int jjb = half * 8;
            for (int k0 = 0; k0 < H_; k0 += 64) {
                __syncthreads();
                const float4* src_h = (const float4*)(hT + k0 * B_);
                const float4* src_a = (const float4*)(g_at + k0 * B_);
                for (int i = tid; i < 2048; i += TPB) {
                    ((float4*)stA)[i] = __ldcg(&src_h[i]);
                    ((float4*)stB)[i] = __ldcg(&src_a[i]);
                }
                __syncthreads();
#pragma unroll 2
                for (int kk = 0; kk < 64; kk++) {
                    ull hv2 = pk2(stA[kk * 128 + b_lane]);
                    ull av2 = pk2(stB[kk * 128 + b_lane]);
                    F4U2 wh0, wh1, wa0, wa1;
                    wh0.f4 = *(const float4*)&sWh[(k0 + kk) * 16 + jjb];
                    wh1.f4 = *(const float4*)&sWh[(k0 + kk) * 16 + jjb + 4];
                    wa0.f4 = *(const float4*)&sWa[(k0 + kk) * 16 + jjb];
                    wa1.f4 = *(const float4*)&sWa[(k0 + kk) * 16 + jjb + 4];
                    fma2(acc2[0], wh0.u.a, hv2); fma2(acc2[1], wh0.u.b, hv2);
                    fma2(acc2[2], wh1.u.a, hv2); fma2(acc2[3], wh1.u.b, hv2);
                    fma2(acc2[0], wa0.u.a, av2); fma2(acc2[1], wa0.u.b, av2);
                    fma2(acc2[2], wa1.u.a, av2); fma2(acc2[3], wa1.u.b, av2);
                }
            }
#pragma unroll
            for (int p2 = 0; p2 < 4; p2++) {
                float lo, hi;
                upk2(acc2[p2], lo, hi);
                int jj0 = jjb + p2 * 2;
                int jl = (jj0 >> 2) * 512 + cta * 4 + (jj0 & 3);
                int jh2 = ((jj0 + 1) >> 2) * 512 + cta * 4 + ((jj0 + 1) & 3);
                sPre[jj0 * 128 + b_lane] =
                    lo + __ldcg(&g_PxT[((size_t)t * H4_ + jl) * B_ + b_lane]);
                sPre[(jj0 + 1) * 128 + b_lane] =
                    hi + __ldcg(&g_PxT[((size_t)t * H4_ + jh2) * B_ + b_lane]);
            }
            __syncthreads();
            if (half == 0) {
                int b = b_lane;
#pragma unroll
                for (int d = 0; d < 4; d++) {
                    float pi = sPre[(0 + d) * 128 + b];
                    float pf = sPre[(4 + d) * 128 + b];
                    float po = sPre[(8 + d) * 128 + b];
                    float pg = sPre[(12 + d) * 128 + b];
                    float iv = 1.f / (1.f + expf(-pi));
                    float fv = 1.f / (1.f + expf(-pf));
                    float ov = 1.f / (1.f + expf(-po));
                    float gv = tanhf(pg);
                    int col = cta * 4 + d;
                    float cold = __ldcg(&g_c[col * B_ + b]);
                    float cnew = cold * fv + iv * gv;
                    float hnew = ov * tanhf(cnew);
                    g_c[col * B_ + b] = cnew;
                    hTn[col * B_ + b] = hnew;
                    out[((size_t)t * B_ + b) * H_ + col] = hnew;
                }
            }
        }
        grid_bar();
    }
}

// ---------------- launch ----------------
extern "C" void kernel_launch(void* const* d_in, const int* in_sizes, int n_in,
                              void* d_out, int out_size) {
    const float* x  = (const float*)d_in[0];
    const float* Wi = (const float*)d_in[1];
    const float* bi = (const float*)d_in[2];
    const float* Wh = (const float*)d_in[3];
    const float* Wv = (const float*)d_in[4];
    const float* bv = (const float*)d_in[5];
    const float* Wq = (const float*)d_in[6];
    const float* bq = (const float*)d_in[7];
    const float* Wa = (const float*)d_in[8];
    const float* ba = (const float*)d_in[9];
    float* out = (float*)d_out;

    static const int PRE_SMEM = 128 * 129 * 4;  // 66048 B
    cudaFuncSetAttribute(precompA, cudaFuncAttributeMaxDynamicSharedMemorySize, PRE_SMEM);
    cudaFuncSetAttribute(precompB, cudaFuncAttributeMaxDynamicSharedMemorySize, PRE_SMEM);
    cudaFuncSetAttribute(larnn_main, cudaFuncAttributeMaxDynamicSharedMemorySize, SM_BYTES);

    precompA<<<dim3(T_, H4_ / 32), TPB, PRE_SMEM>>>(x, Wi, bi, ba);
    precompB<<<dim3(T_, H_ / 32), TPB, PRE_SMEM>>>(x, Wq, bq);
    larnn_main<<<NBLK, TPB, SM_BYTES>>>(Wh, Wv, bv, Wq, Wa, out);
}

// round 7
// speedup vs baseline: 1.4001x; 1.3990x over previous
#include <cuda_runtime.h>
#include <cuda_bf16.h>
#include <math.h>

#define T_  128
#define B_  128
#define I_  128
#define H_  512
#define W_  16
#define H4_ 2048
#define NBLK 128
#define TPB_MAIN 128
#define TPB_PRE 256

typedef unsigned long long ull;

// ---------------- device globals (static scratch; no allocs) ----------------
__device__ __align__(16) float g_PxT[(size_t)T_ * H4_ * B_];  // [t][j][b]
__device__ __align__(16) float g_QxT[(size_t)T_ * H_ * B_];   // [t][q][b]
__device__ __align__(16) float g_Vbuf[(size_t)W_ * B_ * H_];  // [w][b][k]
__device__ __align__(16) float g_h[2][H_ * B_];               // [k][b], double buffered
__device__ __align__(16) float g_c[H_ * B_];                  // [k][b]
__device__ __align__(16) float g_q[B_ * H_];                  // [b][q]
__device__ __align__(16) float g_p[B_ * W_];                  // [b][w]

__device__ unsigned g_cnt = 0;
__device__ volatile unsigned g_gen = 0;

// ---------------- packed fp32x2 helpers ----------------
__device__ __forceinline__ ull pk2(float x) {
    ull r; asm("mov.b64 %0, {%1, %2};" : "=l"(r) : "f"(x), "f"(x)); return r;
}
__device__ __forceinline__ ull pk2b(float lo, float hi) {
    ull r; asm("mov.b64 %0, {%1, %2};" : "=l"(r) : "f"(lo), "f"(hi)); return r;
}
__device__ __forceinline__ void fma2(ull& d, ull a, ull b) {
    asm("fma.rn.f32x2 %0, %1, %2, %3;" : "=l"(d) : "l"(a), "l"(b), "l"(d));
}
__device__ __forceinline__ ull add2(ull a, ull b) {
    ull r; asm("add.rn.f32x2 %0, %1, %2;" : "=l"(r) : "l"(a), "l"(b)); return r;
}
__device__ __forceinline__ void upk2(ull v, float& lo, float& hi) {
    asm("mov.b64 {%0, %1}, %2;" : "=f"(lo), "=f"(hi) : "l"(v));
}
union F4U2 { float4 f4; struct { ull a, b; } u; };

__device__ __forceinline__ float sigf(float x) {
    return __fdividef(1.f, 1.f + __expf(-x));
}

// ---------------- grid barrier (all 128 CTAs resident) ----------------
__device__ __forceinline__ void grid_bar() {
    __syncthreads();
    if (threadIdx.x == 0) {
        __threadfence();
        unsigned gen = g_gen;
        if (atomicAdd(&g_cnt, 1u) == NBLK - 1u) {
            g_cnt = 0;
            __threadfence();
            g_gen = gen + 1u;
        } else {
            while (g_gen == gen) { __nanosleep(32); }
        }
        __threadfence();
    }
    __syncthreads();
}

// ---------------- merged precompute ----------------
// by<64: PxT[t][j][b] = x_t@Wi + bi + ba   (j0 = by*32)
// by>=64: QxT[t][q][b] = x_t@Wq[:I] + bq   (j0 = (by-64)*32)
__global__ void precomp(const float* __restrict__ x, const float* __restrict__ Wi,
                        const float* __restrict__ bi, const float* __restrict__ ba,
                        const float* __restrict__ Wq, const float* __restrict__ bq) {
    extern __shared__ float xs[];          // [128][129]
    __shared__ float Ws[128][32];
    int t = blockIdx.x, by = blockIdx.y;
    bool isQ = (by >= 64);
    int j0 = (isQ ? (by - 64) : by) * 32;
    const float* xt = x + (size_t)t * B_ * I_;
    for (int i = threadIdx.x; i < B_ * I_; i += TPB_PRE)
        xs[(i >> 7) * 129 + (i & 127)] = xt[i];
    for (int i = threadIdx.x; i < 128 * 32; i += TPB_PRE) {
        int k = i >> 5, jl = i & 31;
        Ws[k][jl] = isQ ? Wq[k * H_ + j0 + jl] : Wi[k * H4_ + j0 + jl];
    }
    __syncthreads();
    int b = threadIdx.x & 127, jh = (threadIdx.x >> 7) * 16;
    ull acc[8];
#pragma unroll
    for (int p = 0; p < 8; p++) acc[p] = 0ull;
    for (int k = 0; k < I_; k++) {
        ull xv2 = pk2(xs[b * 129 + k]);
        F4U2 w0, w1, w2, w3;
        w0.f4 = *(const float4*)&Ws[k][jh + 0];
        w1.f4 = *(const float4*)&Ws[k][jh + 4];
        w2.f4 = *(const float4*)&Ws[k][jh + 8];
        w3.f4 = *(const float4*)&Ws[k][jh + 12];
        fma2(acc[0], w0.u.a, xv2); fma2(acc[1], w0.u.b, xv2);
        fma2(acc[2], w1.u.a, xv2); fma2(acc[3], w1.u.b, xv2);
        fma2(acc[4], w2.u.a, xv2); fma2(acc[5], w2.u.b, xv2);
        fma2(acc[6], w3.u.a, xv2); fma2(acc[7], w3.u.b, xv2);
    }
#pragma unroll
    for (int p = 0; p < 8; p++) {
        float lo, hi; upk2(acc[p], lo, hi);
        int j = j0 + jh + p * 2;
        if (isQ) {
            g_QxT[((size_t)t * H_ + j) * B_ + b]     = lo + bq[j];
            g_QxT[((size_t)t * H_ + j + 1) * B_ + b] = hi + bq[j + 1];
        } else {
            g_PxT[((size_t)t * H4_ + j) * B_ + b]     = lo + bi[j] + ba[j];
            g_PxT[((size_t)t * H4_ + j + 1) * B_ + b] = hi + bi[j + 1] + ba[j + 1];
        }
    }
}

// ---------------- main persistent kernel ----------------
// dyn smem (floats): sWh[8192] sWf[8192] sWv[2048] sWq[2048] sVWa[32768]
#define SM_WH 0
#define SM_WF 8192
#define SM_WV 16384
#define SM_WQ 18432
#define SM_VWA 20480
#define SM_FLOATS (20480 + 32768)
#define SM_BYTES (SM_FLOATS * 4)

__device__ __forceinline__ void stepk(const float* sWh, const float* sWf,
                                      const float* sWv, const float* sWq,
                                      int k, float hv, float cv,
                                      ull* aWh, ull* aWf, ull* aV, ull* aQ) {
    ull h2 = pk2(hv), c2 = pk2(cv);
    F4U2 w;
    const float* ph = sWh + k * 16;
    const float* pf = sWf + k * 16;
    w.f4 = *(const float4*)(ph + 0);  fma2(aWh[0], w.u.a, h2); fma2(aWh[1], w.u.b, h2);
    w.f4 = *(const float4*)(ph + 4);  fma2(aWh[2], w.u.a, h2); fma2(aWh[3], w.u.b, h2);
    w.f4 = *(const float4*)(ph + 8);  fma2(aWh[4], w.u.a, h2); fma2(aWh[5], w.u.b, h2);
    w.f4 = *(const float4*)(ph + 12); fma2(aWh[6], w.u.a, h2); fma2(aWh[7], w.u.b, h2);
    w.f4 = *(const float4*)(pf + 0);  fma2(aWf[0], w.u.a, c2); fma2(aWf[1], w.u.b, c2);
    w.f4 = *(const float4*)(pf + 4);  fma2(aWf[2], w.u.a, c2); fma2(aWf[3], w.u.b, c2);
    w.f4 = *(const float4*)(pf + 8);  fma2(aWf[4], w.u.a, c2); fma2(aWf[5], w.u.b, c2);
    w.f4 = *(const float4*)(pf + 12); fma2(aWf[6], w.u.a, c2); fma2(aWf[7], w.u.b, c2);
    w.f4 = *(const float4*)(sWv + k * 4); fma2(aV[0], w.u.a, c2); fma2(aV[1], w.u.b, c2);
    w.f4 = *(const float4*)(sWq + k * 4); fma2(aQ[0], w.u.a, h2); fma2(aQ[1], w.u.b, h2);
}

__global__ void __launch_bounds__(TPB_MAIN, 1)
larnn_main(const float* __restrict__ Wh, const float* __restrict__ Wv,
           const float* __restrict__ bv, const float* __restrict__ Wq,
           const float* __restrict__ Wa, float* __restrict__ out) {
    extern __shared__ float sm[];
    float* sWh = sm + SM_WH;
    float* sWf = sm + SM_WF;
    float* sWv = sm + SM_WV;
    float* sWq = sm + SM_WQ;
    float* sVWa = sm + SM_VWA;                 // [w][jp8][b128] as ull
    ull* sVWaU = (ull*)sVWa;
    __shared__ float sQ[H_];
    __shared__ float sSc[W_];
    __shared__ ull sBvaU[8];
    __shared__ ull sBvU[2];

    const int cta = blockIdx.x;
    const int tid = threadIdx.x;
    const int b = tid;                          // 0..127
    const int cta4 = cta * 4;
    const float isdk = 0.04419417382415922f;    // 1/sqrt(512)
#define COLOF(jj) ((((jj) >> 2) * 512) + cta4 + ((jj) & 3))

    // ---- resident weights ----
    for (int i = tid; i < 8192; i += TPB_MAIN) {
        int k = i >> 4, jj = i & 15;
        sWh[i] = Wh[k * H4_ + COLOF(jj)];
    }
    for (int i = tid; i < 2048; i += TPB_MAIN) {
        int k = i >> 2, d = i & 3;
        sWv[i] = Wv[k * H_ + cta4 + d];
        sWq[i] = Wq[(I_ + k) * H_ + cta4 + d];
    }
    // ---- stage Wa column-slice into scratch (low part of sVWa) ----
    float* WaSl = sVWa;                         // [512][16]
    for (int i = tid; i < 8192; i += TPB_MAIN) {
        int m = i >> 4, jj = i & 15;
        WaSl[i] = Wa[m * H4_ + COLOF(jj)];
    }
    __syncthreads();
    // ---- bva = bv@Wa (owned cols), bv pairs ----
    if (tid < 8) {
        float lo = 0.f, hi = 0.f;
        for (int k = 0; k < H_; k++) {
            float bvk = bv[k];
            lo += bvk * WaSl[k * 16 + tid * 2];
            hi += bvk * WaSl[k * 16 + tid * 2 + 1];
        }
        sBvaU[tid] = pk2b(lo, hi);
    } else if (tid < 10) {
        int d0 = (tid - 8) * 2;
        sBvU[tid - 8] = pk2b(bv[cta4 + d0], bv[cta4 + d0 + 1]);
    }
    // ---- Wf = Wv @ Wa (owned 16 cols) ----
    {
        float* WvT = sVWa + 8192;               // [512][33]
        ull accf[4][8];
#pragma unroll
        for (int kk = 0; kk < 4; kk++)
#pragma unroll
            for (int jp = 0; jp < 8; jp++) accf[kk][jp] = 0ull;
        for (int mb = 0; mb < 16; mb++) {
            __syncthreads();
            for (int i = tid; i < 512 * 32; i += TPB_MAIN) {
                int k = i >> 5, ii = i & 31;
                WvT[k * 33 + ii] = Wv[k * H_ + mb * 32 + ii];
            }
            __syncthreads();
            for (int ii = 0; ii < 32; ii++) {
                int m = mb * 32 + ii;
                F4U2 w0, w1, w2, w3;
                w0.f4 = *(const float4*)&WaSl[m * 16 + 0];
                w1.f4 = *(const float4*)&WaSl[m * 16 + 4];
                w2.f4 = *(const float4*)&WaSl[m * 16 + 8];
                w3.f4 = *(const float4*)&WaSl[m * 16 + 12];
#pragma unroll
                for (int kk = 0; kk < 4; kk++) {
                    ull v2 = pk2(WvT[(tid + 128 * kk) * 33 + ii]);
                    fma2(accf[kk][0], w0.u.a, v2); fma2(accf[kk][1], w0.u.b, v2);
                    fma2(accf[kk][2], w1.u.a, v2); fma2(accf[kk][3], w1.u.b, v2);
                    fma2(accf[kk][4], w2.u.a, v2); fma2(accf[kk][5], w2.u.b, v2);
                    fma2(accf[kk][6], w3.u.a, v2); fma2(accf[kk][7], w3.u.b, v2);
                }
            }
        }
        __syncthreads();
#pragma unroll
        for (int kk = 0; kk < 4; kk++) {
            int k = tid + 128 * kk;
#pragma unroll
            for (int jp = 0; jp < 8; jp++) {
                float lo, hi; upk2(accf[kk][jp], lo, hi);
                sWf[k * 16 + jp * 2] = lo;
                sWf[k * 16 + jp * 2 + 1] = hi;
            }
        }
    }
    __syncthreads();
    // ---- zero VWa cache + global init ----
    for (int i = tid; i < 32768; i += TPB_MAIN) sVWa[i] = 0.f;
#pragma unroll
    for (int d = 0; d < 4; d++) {
        g_h[0][(cta4 + d) * B_ + b] = 0.f;
        g_c[(cta4 + d) * B_ + b] = 0.f;
    }
    for (int w = 0; w < W_; w++)
        *(float4*)&g_Vbuf[((size_t)w * B_ + b) * H_ + cta4] = make_float4(0.f, 0.f, 0.f, 0.f);
    grid_bar();

    // ================= time loop =================
    for (int t = 0; t < T_; t++) {
        const float* hT = g_h[t & 1];
        float* hTn = g_h[(t & 1) ^ 1];

        // ===== Phase A: fused h@Wh, c@Wf(+bva), c@Wv(+bv), h@WqH(+Qx) =====
        ull aWh[8], aWf[8], aV[2], aQ[2];
#pragma unroll
        for (int jp = 0; jp < 8; jp++) { aWh[jp] = 0ull; aWf[jp] = sBvaU[jp]; }
        aV[0] = sBvU[0]; aV[1] = sBvU[1];
        {
            float q0 = __ldg(&g_QxT[((size_t)t * H_ + cta4 + 0) * B_ + b]);
            float q1 = __ldg(&g_QxT[((size_t)t * H_ + cta4 + 1) * B_ + b]);
            float q2 = __ldg(&g_QxT[((size_t)t * H_ + cta4 + 2) * B_ + b]);
            float q3 = __ldg(&g_QxT[((size_t)t * H_ + cta4 + 3) * B_ + b]);
            aQ[0] = pk2b(q0, q1); aQ[1] = pk2b(q2, q3);
        }
        float hA[8], cA[8], hB[8], cB[8];
#define LOADBLK(HH, CC, KB) do { int _kb = (KB); \
        _Pragma("unroll") \
        for (int u = 0; u < 8; u++) { \
            HH[u] = __ldcg(&hT[(_kb * 8 + u) * B_ + b]); \
            CC[u] = __ldcg(&g_c[(_kb * 8 + u) * B_ + b]); } } while (0)
#define COMPBLK(HH, CC, KB) do { int _kb = (KB); \
        _Pragma("unroll") \
        for (int u = 0; u < 8; u++) \
            stepk(sWh, sWf, sWv, sWq, _kb * 8 + u, HH[u], CC[u], aWh, aWf, aV, aQ); } while (0)

        LOADBLK(hA, cA, 0);
        for (int kb = 0; kb < 64; kb += 2) {
            LOADBLK(hB, cB, kb + 1);
            COMPBLK(hA, cA, kb);
            LOADBLK(hA, cA, (kb + 2) & 63);
            COMPBLK(hB, cB, kb + 1);
        }
        // epilogue: VWa slot (smem, private), Vnew + Q (global)
        int slot = t & (W_ - 1);
#pragma unroll
        for (int jp = 0; jp < 8; jp++)
            sVWaU[(slot * 8 + jp) * 128 + b] = aWf[jp];
        {
            float4 v; upk2(aV[0], v.x, v.y); upk2(aV[1], v.z, v.w);
            __stcg((float4*)&g_Vbuf[((size_t)slot * B_ + b) * H_ + cta4], v);
            float4 q; upk2(aQ[0], q.x, q.y); upk2(aQ[1], q.z, q.w);
            __stcg((float4*)&g_q[(size_t)b * H_ + cta4], q);
        }
        grid_bar();

        // ===== Phase B: attention scores+softmax for row bb=cta =====
        {
            const int bb = cta;
            ((float4*)sQ)[tid] = __ldcg(&((const float4*)(g_q + (size_t)bb * H_))[tid]);
            __syncthreads();
            int warp = tid >> 5, lane = tid & 31;
#pragma unroll
            for (int wi = 0; wi < 4; wi++) {
                int w = warp * 4 + wi;
                const float4* Vp = (const float4*)(g_Vbuf + ((size_t)w * B_ + bb) * H_);
                float s = 0.f;
#pragma unroll
                for (int c4 = 0; c4 < 4; c4++) {
                    float4 v = __ldcg(&Vp[lane + c4 * 32]);
                    float4 q = ((const float4*)sQ)[lane + c4 * 32];
                    s += v.x * q.x + v.y * q.y + v.z * q.z + v.w * q.w;
                }
#pragma unroll
                for (int o = 16; o; o >>= 1) s += __shfl_xor_sync(0xffffffffu, s, o);
                if (lane == 0) sSc[w] = s * isdk;
            }
            __syncthreads();
            if (tid < 16) {
                int nv = (t + 1 < W_) ? (t + 1) : W_;
                float v = (tid < nv) ? sSc[tid] : -1e30f;
                float m = v;
#pragma unroll
                for (int o = 8; o; o >>= 1) m = fmaxf(m, __shfl_xor_sync(0xffffu, m, o));
                float e = (tid < nv) ? __expf(v - m) : 0.f;
                float ssum = e;
#pragma unroll
                for (int o = 8; o; o >>= 1) ssum += __shfl_xor_sync(0xffffu, ssum, o);
                __stcg(&g_p[bb * W_ + tid], e / ssum);
            }
        }
        grid_bar();

        // ===== Phase C: preact = Px + hWh(regs) + p@VWa; gates; update =====
        {
            float pw[16];
            {
                float4 p0 = __ldcg((const float4*)&g_p[b * W_ + 0]);
                float4 p1 = __ldcg((const float4*)&g_p[b * W_ + 4]);
                float4 p2 = __ldcg((const float4*)&g_p[b * W_ + 8]);
                float4 p3 = __ldcg((const float4*)&g_p[b * W_ + 12]);
                pw[0] = p0.x; pw[1] = p0.y; pw[2] = p0.z; pw[3] = p0.w;
                pw[4] = p1.x; pw[5] = p1.y; pw[6] = p1.z; pw[7] = p1.w;
                pw[8] = p2.x; pw[9] = p2.y; pw[10] = p2.z; pw[11] = p2.w;
                pw[12] = p3.x; pw[13] = p3.y; pw[14] = p3.z; pw[15] = p3.w;
            }
            ull aAt[8];
#pragma unroll
            for (int jp = 0; jp < 8; jp++) aAt[jp] = 0ull;
#pragma unroll
            for (int w = 0; w < W_; w++) {
                ull p2w = pk2(pw[w]);
#pragma unroll
                for (int jp = 0; jp < 8; jp++)
                    fma2(aAt[jp], sVWaU[(w * 8 + jp) * 128 + b], p2w);
            }
            float pre[16];
#pragma unroll
            for (int jp = 0; jp < 8; jp++) {
                ull s2 = add2(aWh[jp], aAt[jp]);
                float lo, hi; upk2(s2, lo, hi);
                int jj = jp * 2;
                pre[jj]     = lo + __ldg(&g_PxT[((size_t)t * H4_ + COLOF(jj)) * B_ + b]);
                pre[jj + 1] = hi + __ldg(&g_PxT[((size_t)t * H4_ + COLOF(jj + 1)) * B_ + b]);
            }
            float4 ov;
#pragma unroll
            for (int d = 0; d < 4; d++) {
                float ig = sigf(pre[d]);
                float fg = sigf(pre[4 + d]);
                float og = sigf(pre[8 + d]);
                float gg = tanhf(pre[12 + d]);
                float cold = __ldcg(&g_c[(cta4 + d) * B_ + b]);
                float cn = cold * fg + ig * gg;
                float hn = og * tanhf(cn);
                __stcg(&g_c[(cta4 + d) * B_ + b], cn);
                __stcg(&hTn[(cta4 + d) * B_ + b], hn);
                (&ov.x)[d] = hn;
            }
            __stcg((float4*)&out[((size_t)t * B_ + b) * H_ + cta4], ov);
        }
        grid_bar();
    }
#undef LOADBLK
#undef COMPBLK
#undef COLOF
}

// ---------------- launch ----------------
extern "C" void kernel_launch(void* const* d_in, const int* in_sizes, int n_in,
                              void* d_out, int out_size) {
    const float* x  = (const float*)d_in[0];
    const float* Wi = (const float*)d_in[1];
    const float* bi = (const float*)d_in[2];
    const float* Wh = (const float*)d_in[3];
    const float* Wv = (const float*)d_in[4];
    const float* bv = (const float*)d_in[5];
    const float* Wq = (const float*)d_in[6];
    const float* bq = (const float*)d_in[7];
    const float* Wa = (const float*)d_in[8];
    const float* ba = (const float*)d_in[9];
    float* out = (float*)d_out;

    static const int PRE_SMEM = 128 * 129 * 4;  // 66048 B
    cudaFuncSetAttribute(precomp, cudaFuncAttributeMaxDynamicSharedMemorySize, PRE_SMEM);
    cudaFuncSetAttribute(larnn_main, cudaFuncAttributeMaxDynamicSharedMemorySize, SM_BYTES);

    precomp<<<dim3(T_, 80), TPB_PRE, PRE_SMEM>>>(x, Wi, bi, ba, Wq, bq);
    larnn_main<<<NBLK, TPB_MAIN, SM_BYTES>>>(Wh, Wv, bv, Wq, Wa, out);
}

// round 11
// speedup vs baseline: 1.4851x; 1.0607x over previous
#include <cuda_runtime.h>
#include <cuda_bf16.h>
#include <math.h>

#define T_  128
#define B_  128
#define I_  128
#define H_  512
#define W_  16
#define H4_ 2048
#define NBLK 128
#define TPB_MAIN 256
#define TPB_PRE 256

typedef unsigned long long ull;

// ---------------- device globals (static scratch; no allocs) ----------------
__device__ __align__(16) float g_PxT[(size_t)T_ * H4_ * B_];  // [t][j][b]
__device__ __align__(16) float g_QxT[(size_t)T_ * H_ * B_];   // [t][q][b]
__device__ __align__(16) float g_Vbuf[(size_t)W_ * B_ * H_];  // [w][b][k]
__device__ __align__(16) float g_h[2][H_ * B_];               // [k][b]
__device__ __align__(16) float g_c[H_ * B_];                  // [k][b]
__device__ __align__(16) float g_q[B_ * H_];                  // [b][q]
__device__ __align__(16) float g_p[B_ * W_];                  // [b][w]

__device__ unsigned g_cnt = 0;
__device__ volatile unsigned g_gen = 0;

// ---------------- packed fp32x2 helpers ----------------
__device__ __forceinline__ ull pk2(float x) {
    ull r; asm("mov.b64 %0, {%1, %2};" : "=l"(r) : "f"(x), "f"(x)); return r;
}
__device__ __forceinline__ ull pk2b(float lo, float hi) {
    ull r; asm("mov.b64 %0, {%1, %2};" : "=l"(r) : "f"(lo), "f"(hi)); return r;
}
__device__ __forceinline__ void fma2(ull& d, ull a, ull b) {
    asm("fma.rn.f32x2 %0, %1, %2, %3;" : "=l"(d) : "l"(a), "l"(b), "l"(d));
}
__device__ __forceinline__ void upk2(ull v, float& lo, float& hi) {
    asm("mov.b64 {%0, %1}, %2;" : "=f"(lo), "=f"(hi) : "l"(v));
}
union F4U2 { float4 f4; struct { ull a, b; } u; };

__device__ __forceinline__ float sigf(float x) {
    return __fdividef(1.f, 1.f + __expf(-x));
}

// ---------------- grid barrier (R7-validated; survives graph replays) -------
__device__ __forceinline__ void grid_bar() {
    __syncthreads();
    if (threadIdx.x == 0) {
        __threadfence();
        unsigned gen = g_gen;
        if (atomicAdd(&g_cnt, 1u) == NBLK - 1u) {
            g_cnt = 0;
            __threadfence();
            g_gen = gen + 1u;
        } else {
            while (g_gen == gen) { __nanosleep(32); }
        }
        __threadfence();
    }
    __syncthreads();
}

// ---------------- merged precompute (R7-validated, verbatim) ----------------
// by<64: PxT[t][j][b] = x_t@Wi + bi + ba   (j0 = by*32)
// by>=64: QxT[t][q][b] = x_t@Wq[:I] + bq   (j0 = (by-64)*32)
__global__ void precomp(const float* __restrict__ x, const float* __restrict__ Wi,
                        const float* __restrict__ bi, const float* __restrict__ ba,
                        const float* __restrict__ Wq, const float* __restrict__ bq) {
    extern __shared__ float xs[];          // [128][129]
    __shared__ __align__(16) float Ws[128][32];
    int t = blockIdx.x, by = blockIdx.y;
    bool isQ = (by >= 64);
    int j0 = (isQ ? (by - 64) : by) * 32;
    const float* xt = x + (size_t)t * B_ * I_;
    for (int i = threadIdx.x; i < B_ * I_; i += TPB_PRE)
        xs[(i >> 7) * 129 + (i & 127)] = xt[i];
    for (int i = threadIdx.x; i < 128 * 32; i += TPB_PRE) {
        int k = i >> 5, jl = i & 31;
        Ws[k][jl] = isQ ? Wq[k * H_ + j0 + jl] : Wi[k * H4_ + j0 + jl];
    }
    __syncthreads();
    int b = threadIdx.x & 127, jh = (threadIdx.x >> 7) * 16;
    ull acc[8];
#pragma unroll
    for (int p = 0; p < 8; p++) acc[p] = 0ull;
    for (int k = 0; k < I_; k++) {
        ull xv2 = pk2(xs[b * 129 + k]);
        F4U2 w0, w1, w2, w3;
        w0.f4 = *(const float4*)&Ws[k][jh + 0];
        w1.f4 = *(const float4*)&Ws[k][jh + 4];
        w2.f4 = *(const float4*)&Ws[k][jh + 8];
        w3.f4 = *(const float4*)&Ws[k][jh + 12];
        fma2(acc[0], w0.u.a, xv2); fma2(acc[1], w0.u.b, xv2);
        fma2(acc[2], w1.u.a, xv2); fma2(acc[3], w1.u.b, xv2);
        fma2(acc[4], w2.u.a, xv2); fma2(acc[5], w2.u.b, xv2);
        fma2(acc[6], w3.u.a, xv2); fma2(acc[7], w3.u.b, xv2);
    }
#pragma unroll
    for (int p = 0; p < 8; p++) {
        float lo, hi; upk2(acc[p], lo, hi);
        int j = j0 + jh + p * 2;
        if (isQ) {
            g_QxT[((size_t)t * H_ + j) * B_ + b]     = lo + bq[j];
            g_QxT[((size_t)t * H_ + j + 1) * B_ + b] = hi + bq[j + 1];
        } else {
            g_PxT[((size_t)t * H4_ + j) * B_ + b]     = lo + bi[j] + ba[j];
            g_PxT[((size_t)t * H4_ + j + 1) * B_ + b] = hi + bi[j + 1] + ba[j + 1];
        }
    }
}

// ---------------- main persistent kernel ----------------
// dyn smem (floats): sWh[8192] sWf[8192] sWv[2048] sWq[2048] sVWa[32768] sPre[2048]
#define SM_WH 0
#define SM_WF 8192
#define SM_WV 16384
#define SM_WQ 18432
#define SM_VWA 20480
#define SM_PRE (20480 + 32768)
#define SM_FLOATS (SM_PRE + 2048)
#define SM_BYTES (SM_FLOATS * 4)

// j-split step: this thread owns 8 preact columns (jjb..jjb+7) of Wh and Wf,
// plus Wv (half 0, input c) or WqH (half 1, input h).
__device__ __forceinline__ void stepk2(const float* sWhB, const float* sWfB,
                                       const float* sWvq, int k, float hv, float cv,
                                       int half, ull* aWh, ull* aWf, ull* aVQ) {
    ull h2 = pk2(hv), c2 = pk2(cv);
    ull x2 = half ? h2 : c2;
    F4U2 w;
    const float* ph = sWhB + k * 16;
    const float* pf = sWfB + k * 16;
    w.f4 = *(const float4*)(ph + 0);  fma2(aWh[0], w.u.a, h2); fma2(aWh[1], w.u.b, h2);
    w.f4 = *(const float4*)(ph + 4);  fma2(aWh[2], w.u.a, h2); fma2(aWh[3], w.u.b, h2);
    w.f4 = *(const float4*)(pf + 0);  fma2(aWf[0], w.u.a, c2); fma2(aWf[1], w.u.b, c2);
    w.f4 = *(const float4*)(pf + 4);  fma2(aWf[2], w.u.a, c2); fma2(aWf[3], w.u.b, c2);
    w.f4 = *(const float4*)(sWvq + k * 4); fma2(aVQ[0], w.u.a, x2); fma2(aVQ[1], w.u.b, x2);
}

__global__ void __launch_bounds__(TPB_MAIN, 1)
larnn_main(const float* __restrict__ Wh, const float* __restrict__ Wv,
           const float* __restrict__ bv, const float* __restrict__ Wq,
           const float* __restrict__ Wa, float* __restrict__ out) {
    extern __shared__ float sm[];
    float* sWh = sm + SM_WH;
    float* sWf = sm + SM_WF;
    float* sWv = sm + SM_WV;
    float* sWq = sm + SM_WQ;
    float* sVWa = sm + SM_VWA;                 // [w][jp8][b128] as ull
    ull* sVWaU = (ull*)sVWa;
    float* sPre = sm + SM_PRE;                 // [16][128]
    __shared__ __align__(16) float sQ[H_];
    __shared__ __align__(16) float sSc[W_];
    __shared__ __align__(16) ull sBvaU[8];
    __shared__ __align__(16) ull sBvU[2];

    const int cta = blockIdx.x;
    const int tid = threadIdx.x;
    const int b = tid & 127;
    const int half = tid >> 7;
    const int jjb = half * 8;                   // owned preact columns
    const int cta4 = cta * 4;
    const float isdk = 0.04419417382415922f;    // 1/sqrt(512)
#define COLOF(jj) ((((jj) >> 2) * 512) + cta4 + ((jj) & 3))

    // ---- resident weights ----
    for (int i = tid; i < 8192; i += TPB_MAIN) {
        int k = i >> 4, jj = i & 15;
        sWh[i] = Wh[k * H4_ + COLOF(jj)];
    }
    for (int i = tid; i < 2048; i += TPB_MAIN) {
        int k = i >> 2, d = i & 3;
        sWv[i] = Wv[k * H_ + cta4 + d];
        sWq[i] = Wq[(I_ + k) * H_ + cta4 + d];
    }
    // ---- stage Wa column-slice into scratch (low part of sVWa) ----
    float* WaSl = sVWa;                         // [512][16]
    for (int i = tid; i < 8192; i += TPB_MAIN) {
        int m = i >> 4, jj = i & 15;
        WaSl[i] = Wa[m * H4_ + COLOF(jj)];
    }
    __syncthreads();
    // ---- bva = bv@Wa (owned cols), bv pairs ----
    if (tid < 8) {
        float lo = 0.f, hi = 0.f;
        for (int k = 0; k < H_; k++) {
            float bvk = bv[k];
            lo += bvk * WaSl[k * 16 + tid * 2];
            hi += bvk * WaSl[k * 16 + tid * 2 + 1];
        }
        sBvaU[tid] = pk2b(lo, hi);
    } else if (tid < 10) {
        int d0 = (tid - 8) * 2;
        sBvU[tid - 8] = pk2b(bv[cta4 + d0], bv[cta4 + d0 + 1]);
    }
    // ---- Wf = Wv @ Wa (owned 16 cols) ----
    {
        float* WvT = sVWa + 8192;               // [512][33]
        ull accf[2][8];
#pragma unroll
        for (int kk = 0; kk < 2; kk++)
#pragma unroll
            for (int jp = 0; jp < 8; jp++) accf[kk][jp] = 0ull;
        for (int mb = 0; mb < 16; mb++) {
            __syncthreads();
            for (int i = tid; i < 512 * 32; i += TPB_MAIN) {
                int k = i >> 5, ii = i & 31;
                WvT[k * 33 + ii] = Wv[k * H_ + mb * 32 + ii];
            }
            __syncthreads();
            for (int ii = 0; ii < 32; ii++) {
                int m = mb * 32 + ii;
                F4U2 w0, w1, w2, w3;
                w0.f4 = *(const float4*)&WaSl[m * 16 + 0];
                w1.f4 = *(const float4*)&WaSl[m * 16 + 4];
                w2.f4 = *(const float4*)&WaSl[m * 16 + 8];
                w3.f4 = *(const float4*)&WaSl[m * 16 + 12];
#pragma unroll
                for (int kk = 0; kk < 2; kk++) {
                    ull v2 = pk2(WvT[(tid + 256 * kk) * 33 + ii]);
                    fma2(accf[kk][0], w0.u.a, v2); fma2(accf[kk][1], w0.u.b, v2);
                    fma2(accf[kk][2], w1.u.a, v2); fma2(accf[kk][3], w1.u.b, v2);
                    fma2(accf[kk][4], w2.u.a, v2); fma2(accf[kk][5], w2.u.b, v2);
                    fma2(accf[kk][6], w3.u.a, v2); fma2(accf[kk][7], w3.u.b, v2);
                }
            }
        }
        __syncthreads();
#pragma unroll
        for (int kk = 0; kk < 2; kk++) {
            int k = tid + 256 * kk;
#pragma unroll
            for (int jp = 0; jp < 8; jp++) {
                float lo, hi; upk2(accf[kk][jp], lo, hi);
                sWf[k * 16 + jp * 2] = lo;
                sWf[k * 16 + jp * 2 + 1] = hi;
            }
        }
    }
    __syncthreads();
    // ---- zero VWa cache + global init ----
    for (int i = tid; i < 32768; i += TPB_MAIN) sVWa[i] = 0.f;
    for (int i = tid; i < 4 * B_; i += TPB_MAIN) {
        int d = i >> 7, bb2 = i & 127;
        g_h[0][(cta4 + d) * B_ + bb2] = 0.f;
        g_c[(cta4 + d) * B_ + bb2] = 0.f;
    }
    if (half == 0)
        for (int w = 0; w < W_; w++)
            *(float4*)&g_Vbuf[((size_t)w * B_ + b) * H_ + cta4] = make_float4(0.f, 0.f, 0.f, 0.f);
    grid_bar();

    // ================= time loop =================
    for (int t = 0; t < T_; t++) {
        const float* hT = g_h[t & 1];
        float* hTn = g_h[(t & 1) ^ 1];
        const int slot = t & (W_ - 1);

        // ===== Phase A: j-split fused GEMMs (each half owns 8 preact cols) ==
        ull aWh[4], aWf[4], aVQ[2];
#pragma unroll
        for (int jp = 0; jp < 4; jp++) { aWh[jp] = 0ull; aWf[jp] = sBvaU[half * 4 + jp]; }
        if (half == 0) {
            aVQ[0] = sBvU[0]; aVQ[1] = sBvU[1];
        } else {
            float q0 = __ldg(&g_QxT[((size_t)t * H_ + cta4 + 0) * B_ + b]);
            float q1 = __ldg(&g_QxT[((size_t)t * H_ + cta4 + 1) * B_ + b]);
            float q2 = __ldg(&g_QxT[((size_t)t * H_ + cta4 + 2) * B_ + b]);
            float q3 = __ldg(&g_QxT[((size_t)t * H_ + cta4 + 3) * B_ + b]);
            aVQ[0] = pk2b(q0, q1); aVQ[1] = pk2b(q2, q3);
        }
        {
            const float* sWhB = sWh + jjb;
            const float* sWfB = sWf + jjb;
            const float* sWvq = half ? sWq : sWv;
            float hA[8], cA[8], hB[8], cB[8];
#define LOADBLK(HH, CC, KB) do { int _kb = (KB); \
            _Pragma("unroll") \
            for (int u = 0; u < 8; u++) { \
                HH[u] = __ldcg(&hT[(_kb * 8 + u) * B_ + b]); \
                CC[u] = __ldcg(&g_c[(_kb * 8 + u) * B_ + b]); } } while (0)
#define COMPBLK(HH, CC, KB) do { int _kb = (KB); \
            _Pragma("unroll") \
            for (int u = 0; u < 8; u++) \
                stepk2(sWhB, sWfB, sWvq, _kb * 8 + u, HH[u], CC[u], half, aWh, aWf, aVQ); } while (0)
            LOADBLK(hA, cA, 0);
            for (int kb = 0; kb < 64; kb += 2) {
                LOADBLK(hB, cB, kb + 1);
                COMPBLK(hA, cA, kb);
                LOADBLK(hA, cA, (kb + 2) & 63);
                COMPBLK(hB, cB, kb + 1);
            }
#undef LOADBLK
#undef COMPBLK
        }
        // epilogue: each half writes its own 4 VWa pairs; V/Q stores split
#pragma unroll
        for (int jp = 0; jp < 4; jp++)
            sVWaU[(slot * 8 + half * 4 + jp) * 128 + b] = aWf[jp];
        {
            float4 v; upk2(aVQ[0], v.x, v.y); upk2(aVQ[1], v.z, v.w);
            if (half == 0)
                __stcg((float4*)&g_Vbuf[((size_t)slot * B_ + b) * H_ + cta4], v);
            else
                __stcg((float4*)&g_q[(size_t)b * H_ + cta4], v);
        }
        grid_bar();

        // ===== Phase B: attention scores+softmax for row bb=cta =====
        {
            const int bb = cta;
            if (tid < 128)
                ((float4*)sQ)[tid] = __ldcg(&((const float4*)(g_q + (size_t)bb * H_))[tid]);
            __syncthreads();
            int warp = tid >> 5, lane = tid & 31;
#pragma unroll
            for (int wi = 0; wi < 2; wi++) {
                int w = warp * 2 + wi;
                const float4* Vp = (const float4*)(g_Vbuf + ((size_t)w * B_ + bb) * H_);
                float s = 0.f;
#pragma unroll
                for (int c4 = 0; c4 < 4; c4++) {
                    float4 v = __ldcg(&Vp[lane + c4 * 32]);
                    float4 qv = ((const float4*)sQ)[lane + c4 * 32];
                    s += v.x * qv.x + v.y * qv.y + v.z * qv.z + v.w * qv.w;
                }
#pragma unroll
                for (int o = 16; o; o >>= 1) s += __shfl_xor_sync(0xffffffffu, s, o);
                if (lane == 0) sSc[w] = s * isdk;
            }
            __syncthreads();
            if (tid < 16) {
                int nv = (t + 1 < W_) ? (t + 1) : W_;
                float v = (tid < nv) ? sSc[tid] : -1e30f;
                float m = v;
#pragma unroll
                for (int o = 8; o; o >>= 1) m = fmaxf(m, __shfl_xor_sync(0xffffu, m, o));
                float e = (tid < nv) ? __expf(v - m) : 0.f;
                float ssum = e;
#pragma unroll
                for (int o = 8; o; o >>= 1) ssum += __shfl_xor_sync(0xffffu, ssum, o);
                __stcg(&g_p[bb * W_ + tid], e / ssum);
            }
        }
        grid_bar();

        // ===== Phase C: each half builds its 8 preact cols; half0 gates =====
        {
            float4 p0 = __ldcg((const float4*)&g_p[b * W_ + 0]);
            float4 p1 = __ldcg((const float4*)&g_p[b * W_ + 4]);
            float4 p2 = __ldcg((const float4*)&g_p[b * W_ + 8]);
            float4 p3 = __ldcg((const float4*)&g_p[b * W_ + 12]);
            float pw[16] = {p0.x, p0.y, p0.z, p0.w, p1.x, p1.y, p1.z, p1.w,
                            p2.x, p2.y, p2.z, p2.w, p3.x, p3.y, p3.z, p3.w};
            ull aAt[4];
#pragma unroll
            for (int jp = 0; jp < 4; jp++) aAt[jp] = 0ull;
#pragma unroll
            for (int w = 0; w < W_; w++) {
                ull p2w = pk2(pw[w]);
#pragma unroll
                for (int jp = 0; jp < 4; jp++)
                    fma2(aAt[jp], sVWaU[(w * 8 + half * 4 + jp) * 128 + b], p2w);
            }
#pragma unroll
            for (int jp = 0; jp < 4; jp++) {
                ull s2; { s2 = aWh[jp]; fma2(s2, aAt[jp], pk2(1.f)); }
                float lo, hi; upk2(s2, lo, hi);
                int jj = jjb + jp * 2;
                sPre[jj * 128 + b] =
                    lo + __ldg(&g_PxT[((size_t)t * H4_ + COLOF(jj)) * B_ + b]);
                sPre[(jj + 1) * 128 + b] =
                    hi + __ldg(&g_PxT[((size_t)t * H4_ + COLOF(jj + 1)) * B_ + b]);
            }
        }
        __syncthreads();
        if (half == 0) {
            float4 ov;
#pragma unroll
            for (int d = 0; d < 4; d++) {
                float ig = sigf(sPre[(0 + d) * 128 + b]);
                float fg = sigf(sPre[(4 + d) * 128 + b]);
                float og = sigf(sPre[(8 + d) * 128 + b]);
                float gg = tanhf(sPre[(12 + d) * 128 + b]);
                float cold = __ldcg(&g_c[(cta4 + d) * B_ + b]);
                float cn = cold * fg + ig * gg;
                float hn = og * tanhf(cn);
                __stcg(&g_c[(cta4 + d) * B_ + b], cn);
                __stcg(&hTn[(cta4 + d) * B_ + b], hn);
                (&ov.x)[d] = hn;
            }
            __stcg((float4*)&out[((size_t)t * B_ + b) * H_ + cta4], ov);
        }
        grid_bar();
    }
#undef COLOF
}

// ---------------- launch ----------------
extern "C" void kernel_launch(void* const* d_in, const int* in_sizes, int n_in,
                              void* d_out, int out_size) {
    const float* x  = (const float*)d_in[0];
    const float* Wi = (const float*)d_in[1];
    const float* bi = (const float*)d_in[2];
    const float* Wh = (const float*)d_in[3];
    const float* Wv = (const float*)d_in[4];
    const float* bv = (const float*)d_in[5];
    const float* Wq = (const float*)d_in[6];
    const float* bq = (const float*)d_in[7];
    const float* Wa = (const float*)d_in[8];
    const float* ba = (const float*)d_in[9];
    float* out = (float*)d_out;

    static const int PRE_SMEM = 128 * 129 * 4;  // 66048 B
    cudaFuncSetAttribute(precomp, cudaFuncAttributeMaxDynamicSharedMemorySize, PRE_SMEM);
    cudaFuncSetAttribute(larnn_main, cudaFuncAttributeMaxDynamicSharedMemorySize, SM_BYTES);

    precomp<<<dim3(T_, 80), TPB_PRE, PRE_SMEM>>>(x, Wi, bi, ba, Wq, bq);
    larnn_main<<<NBLK, TPB_MAIN, SM_BYTES>>>(Wh, Wv, bv, Wq, Wa, out);
}